// round 4
// baseline (speedup 1.0000x reference)
#include <cuda_runtime.h>
#include <math.h>
#include <stdint.h>

#define C        14
#define NPROD    32                       // producer warp
#define NCONS    256                      // consumer threads
#define NT       (NPROD + NCONS)          // 288
#define TILE     256                      // tasks per tile (1 task = 2 rows = 112 B)
#define NSTAGES  4
#define GRID     148                      // persistent blocks (1/SM)

#define TASK_BYTES   112
#define ARR_BYTES    (TILE * TASK_BYTES)      // 28672
#define STAGE_BYTES  (2 * ARR_BYTES)          // 57344
#define MBAR_OFF     (NSTAGES * STAGE_BYTES)  // 229376
#define SMEM_BYTES   (MBAR_OFF + 2 * NSTAGES * 8)

__device__ float g_partials[GRID];
__device__ unsigned int g_done;   // wraps to 0 each launch

// ---------------- mbarrier / TMA helpers ----------------
__device__ __forceinline__ uint32_t smem_u32(const void* p) {
    uint32_t a;
    asm("{ .reg .u64 t; cvta.to.shared.u64 t, %1; cvt.u32.u64 %0, t; }" : "=r"(a) : "l"(p));
    return a;
}
__device__ __forceinline__ void mbar_init(uint32_t m, uint32_t cnt) {
    asm volatile("mbarrier.init.shared.b64 [%0], %1;" :: "r"(m), "r"(cnt) : "memory");
}
__device__ __forceinline__ void mbar_arrive(uint32_t m) {
    asm volatile("mbarrier.arrive.shared.b64 _, [%0];" :: "r"(m) : "memory");
}
__device__ __forceinline__ void mbar_expect_tx(uint32_t m, uint32_t bytes) {
    asm volatile("mbarrier.arrive.expect_tx.shared.b64 _, [%0], %1;" :: "r"(m), "r"(bytes) : "memory");
}
__device__ __forceinline__ void mbar_wait(uint32_t m, uint32_t parity) {
    uint32_t done;
    asm volatile(
        "{\n\t.reg .pred p;\n\t"
        "mbarrier.try_wait.parity.acquire.cta.shared::cta.b64 p, [%1], %2;\n\t"
        "selp.b32 %0, 1, 0, p;\n\t}"
        : "=r"(done) : "r"(m), "r"(parity) : "memory");
    if (!done) {
        asm volatile(
            "{\n\t.reg .pred P1;\n"
            "W_%=:\n\t"
            "mbarrier.try_wait.parity.acquire.cta.shared::cta.b64 P1, [%0], %1, 0x989680;\n\t"
            "@P1 bra D_%=;\n\t"
            "bra W_%=;\n"
            "D_%=:\n\t}"
            :: "r"(m), "r"(parity) : "memory");
    }
}
__device__ __forceinline__ void bulk_g2s(uint32_t dst, const void* src, uint32_t bytes, uint32_t mbar) {
    asm volatile(
        "cp.async.bulk.shared::cta.global.mbarrier::complete_tx::bytes [%0], [%1], %2, [%3];"
        :: "r"(dst), "l"(src), "r"(bytes), "r"(mbar) : "memory");
}
// --------------------------------------------------------

__device__ __forceinline__ float bce_elem(float x, float t) {
    return fmaf(-x, t, x) + __logf(1.0f + __expf(-x));
}

__device__ float generic_row(const float* xr, const float* tr, const int* g) {
    float b[C], ts[4] = {0.f, 0.f, 0.f, 0.f};
#pragma unroll
    for (int c = 0; c < C; c++) {
        float x = xr[c], t = tr[c];
        b[c] = fmaxf(x, 0.0f) - x * t + log1pf(expf(-fabsf(x)));
#pragma unroll
        for (int j = 1; j < 4; j++) ts[j] += (g[c] == j) ? t : 0.f;
    }
    float row = 0.f;
#pragma unroll
    for (int c = 0; c < C; c++) {
        int gc = g[c];
        row += b[c] * ((gc == 0) ? 1.f : ((ts[gc] > 0.f) ? 1.f : 0.f));
    }
    return row;
}

__device__ __forceinline__ float task_loss(const float4* xp, const float4* tp) {
    float x[28], t[28];
#pragma unroll
    for (int j = 0; j < 7; j++) {
        float4 xv = xp[j], tv = tp[j];
        x[4*j+0] = xv.x; x[4*j+1] = xv.y; x[4*j+2] = xv.z; x[4*j+3] = xv.w;
        t[4*j+0] = tv.x; t[4*j+1] = tv.y; t[4*j+2] = tv.z; t[4*j+3] = tv.w;
    }
    float acc = 0.f;
#pragma unroll
    for (int r = 0; r < 2; r++) {
        const int o = r * C;
        float b[C];
#pragma unroll
        for (int c = 0; c < C; c++) b[c] = bce_elem(x[o + c], t[o + c]);
        float S0 = (b[0] + b[5]) + b[10];
        float S1 = (b[1] + b[2]) + (b[8] + b[12]);
        float S2 = (b[3] + b[4]) + (b[9] + b[13]);
        float S3 = (b[6] + b[7]) + b[11];
        float T1 = (t[o+1] + t[o+2]) + (t[o+8] + t[o+12]);
        float T2 = (t[o+3] + t[o+4]) + (t[o+9] + t[o+13]);
        float T3 = (t[o+6] + t[o+7]) + t[o+11];
        float row = S0;
        row += (T1 > 0.f) ? S1 : 0.f;
        row += (T2 > 0.f) ? S2 : 0.f;
        row += (T3 > 0.f) ? S3 : 0.f;
        acc += row;
    }
    return acc;
}

__global__ __launch_bounds__(NT) void bce_ws_kernel(
    const float* __restrict__ inputs,
    const float* __restrict__ targets,
    const int*   __restrict__ groups,
    float* __restrict__ out,
    long long B, float inv_count)
{
    extern __shared__ char smem[];
    const int tid = threadIdx.x;

    const int EXP[C] = {0, 1, 1, 2, 2, 0, 3, 3, 1, 2, 0, 3, 1, 2};
    int g[C];
    bool fast = true;
#pragma unroll
    for (int c = 0; c < C; c++) { g[c] = groups[c]; fast &= (g[c] == EXP[c]); }

    const long long tasks = B >> 1;
    float acc = 0.0f;

    if (fast) {
        const uint32_t sbase  = smem_u32(smem);
        const uint32_t full0  = sbase + MBAR_OFF;
        const uint32_t empty0 = sbase + MBAR_OFF + NSTAGES * 8;

        if (tid == 0) {
#pragma unroll
            for (int s = 0; s < NSTAGES; s++) {
                mbar_init(full0  + s * 8, 1);
                mbar_init(empty0 + s * 8, NCONS);
            }
        }
        asm volatile("fence.proxy.async.shared::cta;" ::: "memory");
        __syncthreads();

        const long long ntiles = (tasks + TILE - 1) / TILE;
        long long nlocal = 0;
        if ((long long)blockIdx.x < ntiles)
            nlocal = (ntiles - 1 - blockIdx.x) / GRID + 1;

        if (tid == 0) {
            // ---------------- producer (single thread, free-running) ----------
            int ps = 0; uint32_t pp = 1;
            for (long long k = 0; k < nlocal; k++) {
                long long base = (blockIdx.x + k * GRID) * TILE;
                uint32_t ntsk  = (uint32_t)((tasks - base) < TILE ? (tasks - base) : TILE);
                uint32_t bytes = ntsk * TASK_BYTES;
                mbar_wait(empty0 + ps * 8, pp);
                mbar_expect_tx(full0 + ps * 8, 2 * bytes);
                uint32_t dst = sbase + ps * STAGE_BYTES;
                bulk_g2s(dst,             inputs  + base * 28, bytes, full0 + ps * 8);
                bulk_g2s(dst + ARR_BYTES, targets + base * 28, bytes, full0 + ps * 8);
                if (++ps == NSTAGES) { ps = 0; pp ^= 1; }
            }
            // odd-B tail row handled by the otherwise-idle producer of block 0
            if ((B & 1) && blockIdx.x == 0)
                acc += generic_row(inputs + (B - 1) * C, targets + (B - 1) * C, g);
        } else if (tid >= NPROD) {
            // ---------------- consumers (8 warps, 1 task each per tile) -------
            const int ct = tid - NPROD;          // 0..255
            int cs = 0; uint32_t cp = 0;
            for (long long k = 0; k < nlocal; k++) {
                long long base = (blockIdx.x + k * GRID) * TILE;
                long long ntsk = (tasks - base) < TILE ? (tasks - base) : TILE;

                mbar_wait(full0 + cs * 8, cp);
                if (ct < ntsk) {
                    const char* st = smem + cs * STAGE_BYTES + ct * TASK_BYTES;
                    acc += task_loss((const float4*)st,
                                     (const float4*)(st + ARR_BYTES));
                }
                mbar_arrive(empty0 + cs * 8);
                if (++cs == NSTAGES) { cs = 0; cp ^= 1; }
            }
        }
    } else {
        // generic fallback (cold path, correct for any groups)
        const long long gtid   = (long long)blockIdx.x * NT + tid;
        const long long stride = (long long)GRID * NT;
        for (long long row = gtid; row < B; row += stride)
            acc += generic_row(inputs + row * C, targets + row * C, g);
    }

    // ---- block reduction (all NT threads) ----
    __shared__ float warp_s[NT / 32];
    __shared__ bool amLast;
    float v = acc;
#pragma unroll
    for (int o = 16; o > 0; o >>= 1) v += __shfl_down_sync(0xffffffffu, v, o);
    if ((tid & 31) == 0) warp_s[tid >> 5] = v;
    __syncthreads();

    if (tid == 0) {
        float s = 0.f;
#pragma unroll
        for (int i = 0; i < NT / 32; i++) s += warp_s[i];
        g_partials[blockIdx.x] = s;
        __threadfence();
        unsigned int d = atomicInc(&g_done, GRID - 1);
        amLast = (d == GRID - 1);
    }
    __syncthreads();

    if (amLast) {
        float s = 0.f;
        for (int i = tid; i < GRID; i += NT) s += g_partials[i];
#pragma unroll
        for (int o = 16; o > 0; o >>= 1) s += __shfl_down_sync(0xffffffffu, s, o);
        __syncthreads();
        if ((tid & 31) == 0) warp_s[tid >> 5] = s;
        __syncthreads();
        if (tid == 0) {
            float total = 0.f;
#pragma unroll
            for (int i = 0; i < NT / 32; i++) total += warp_s[i];
            out[0] = total * inv_count;
        }
    }
}

extern "C" void kernel_launch(void* const* d_in, const int* in_sizes, int n_in,
                              void* d_out, int out_size)
{
    const float* inputs  = (const float*)d_in[0];
    const float* targets = (const float*)d_in[1];
    const int*   groups  = (const int*)d_in[2];
    float*       out     = (float*)d_out;

    long long B = (long long)in_sizes[0] / C;
    float inv_count = (float)(1.0 / ((double)B * (double)C));

    static bool attr_set = false;
    if (!attr_set) {
        cudaFuncSetAttribute(bce_ws_kernel,
                             cudaFuncAttributeMaxDynamicSharedMemorySize, SMEM_BYTES);
        attr_set = true;
    }
    bce_ws_kernel<<<GRID, NT, SMEM_BYTES>>>(inputs, targets, groups, out, B, inv_count);
}